// round 13
// baseline (speedup 1.0000x reference)
#include <cuda_runtime.h>
#include <cuda_bf16.h>
#include <cuda_fp16.h>
#include <cstdint>

#define NN 50000
#define NE 800000
#define FMAX 220
#define ACTS 224   // fp32 activation row stride (floats) = 896 B = 7 L2 lines

// ---------------- scratch (static device globals; no allocation) ------------
__device__ int   g_is64;
__device__ int   g_src[NE];
__device__ int   g_dst[NE];
__device__ int   g_deg_out[NN];
__device__ int   g_deg_in[NN];
__device__ float g_inv_out[NN];
__device__ float g_inv_in[NN];
__device__ int   g_rowptr[NN + 1];
__device__ int   g_cursor[NN];
__device__ int   g_col[NE];
__device__ __align__(16) float g_bufA[(size_t)NN * FMAX];  // agg output / GEMM A (stride 220)
__device__ __align__(16) float g_act[(size_t)NN * ACTS];   // activations (stride 224)

__device__ __forceinline__ float tanh_fast(float x) {
    float y;
    asm("tanh.approx.f32 %0, %1;" : "=f"(y) : "f"(x));
    return y;
}

// ---------------- dtype detection + conversion ------------------------------
__global__ void k_detect(const int* __restrict__ ei32) {
    int lane = threadIdx.x & 31;
    int nz = (ei32[2 * lane + 1] != 0) ? 1 : 0;
    unsigned any = __ballot_sync(0xFFFFFFFFu, nz);
    if (lane == 0) g_is64 = (any == 0) ? 1 : 0;
}

__global__ void k_convert(const void* __restrict__ ei) {
    int e = blockIdx.x * blockDim.x + threadIdx.x;
    if (e >= NE) return;
    int s, d;
    if (g_is64) {
        const long long* p = (const long long*)ei;
        s = (int)p[e];
        d = (int)p[NE + e];
    } else {
        const int* p = (const int*)ei;
        s = p[e];
        d = p[NE + e];
    }
    g_src[e] = s;
    g_dst[e] = d;
}

// ---------------- graph prep ------------------------------------------------
__global__ void k_init_deg() {
    int i = blockIdx.x * blockDim.x + threadIdx.x;
    if (i < NN) { g_deg_out[i] = 0; g_deg_in[i] = 0; }
}

__global__ void k_degrees() {
    int e = blockIdx.x * blockDim.x + threadIdx.x;
    if (e < NE) {
        int s = g_src[e], d = g_dst[e];
        if ((unsigned)s < NN) atomicAdd(&g_deg_out[s], 1);
        if ((unsigned)d < NN) atomicAdd(&g_deg_in[d], 1);
    }
}

__global__ void k_invsqrt() {
    int i = blockIdx.x * blockDim.x + threadIdx.x;
    if (i < NN) {
        g_inv_out[i] = rsqrtf(fmaxf((float)g_deg_out[i], 1.0f));
        g_inv_in[i]  = rsqrtf(fmaxf((float)g_deg_in[i],  1.0f));
    }
}

__global__ void k_scan() {
    __shared__ int partial[1024];
    const int T = 1024;
    int t = threadIdx.x;
    const int chunk = (NN + T - 1) / T;
    int lo = t * chunk;
    int hi = min(lo + chunk, NN);
    int mysum = 0;
    for (int i = lo; i < hi; i++) mysum += g_deg_in[i];
    partial[t] = mysum;
    __syncthreads();
    for (int off = 1; off < T; off <<= 1) {
        int v = (t >= off) ? partial[t - off] : 0;
        __syncthreads();
        partial[t] += v;
        __syncthreads();
    }
    int run = partial[t] - mysum;
    for (int i = lo; i < hi; i++) {
        g_rowptr[i] = run;
        g_cursor[i] = run;
        run += g_deg_in[i];
    }
    if (t == 0) g_rowptr[NN] = partial[T - 1];
}

__global__ void k_fill() {
    int e = blockIdx.x * blockDim.x + threadIdx.x;
    if (e < NE) {
        int s = g_src[e];
        int d = g_dst[e];
        if ((unsigned)d < NN && (unsigned)s < NN) {
            int pos = atomicAdd(&g_cursor[d], 1);
            g_col[pos] = s;
        }
    }
}

// ---------------- aggregation (scalar fp32, F small), 4-edge batched --------
template <int F, bool SCALE_SRC, bool ADD_BIAS>
__global__ void k_aggregate(const float* __restrict__ in, float* __restrict__ out,
                            const float* __restrict__ bias) {
    int warps_per_block = blockDim.x >> 5;
    int node = blockIdx.x * warps_per_block + (threadIdx.x >> 5);
    if (node >= NN) return;
    int lane = threadIdx.x & 31;
    constexpr int J = (F + 31) / 32;
    float acc[J];
#pragma unroll
    for (int j = 0; j < J; j++) acc[j] = 0.0f;

    int lo = g_rowptr[node];
    int hi = g_rowptr[node + 1];
    int e = lo;
    for (; e + 3 < hi; e += 4) {
        int s0 = g_col[e], s1 = g_col[e + 1], s2 = g_col[e + 2], s3 = g_col[e + 3];
        float c0 = SCALE_SRC ? g_inv_out[s0] : 1.0f;
        float c1 = SCALE_SRC ? g_inv_out[s1] : 1.0f;
        float c2 = SCALE_SRC ? g_inv_out[s2] : 1.0f;
        float c3 = SCALE_SRC ? g_inv_out[s3] : 1.0f;
#pragma unroll
        for (int j = 0; j < J; j++) {
            int f = lane + 32 * j;
            if (f < F) {
                float v0 = in[(size_t)s0 * F + f];
                float v1 = in[(size_t)s1 * F + f];
                float v2 = in[(size_t)s2 * F + f];
                float v3 = in[(size_t)s3 * F + f];
                acc[j] += v0 * c0 + v1 * c1 + v2 * c2 + v3 * c3;
            }
        }
    }
    for (; e < hi; e++) {
        int s = g_col[e];
        float sc = SCALE_SRC ? g_inv_out[s] : 1.0f;
#pragma unroll
        for (int j = 0; j < J; j++) {
            int f = lane + 32 * j;
            if (f < F) acc[j] += in[(size_t)s * F + f] * sc;
        }
    }
    float oi = g_inv_in[node];
    float* orow = out + (size_t)node * F;
#pragma unroll
    for (int j = 0; j < J; j++) {
        int f = lane + 32 * j;
        if (f < F) {
            float v = acc[j] * oi;
            if (ADD_BIAS) v += bias[f];
            orow[f] = v;
        }
    }
}

// ---------------- aggregation F=220 fp32 padded rows, 4-edge batched --------
// in: fp32 rows stride ACTS(=224, 896B = 7 lines). lane loads float4 idx=lane
// and (lane+32 if <55). 4-edge batch -> up to 8 LDG.128 in flight per lane.
// out: fp32 rows stride 220.
__global__ void k_aggregate220_f32(const float* __restrict__ in,
                                   float* __restrict__ out) {
    int warps_per_block = blockDim.x >> 5;
    int node = blockIdx.x * warps_per_block + (threadIdx.x >> 5);
    if (node >= NN) return;
    int lane = threadIdx.x & 31;
    bool has1 = (lane + 32) < 55;

    float4 a0 = make_float4(0.f, 0.f, 0.f, 0.f);
    float4 a1 = make_float4(0.f, 0.f, 0.f, 0.f);

    int lo = g_rowptr[node];
    int hi = g_rowptr[node + 1];
    int e = lo;
    for (; e + 3 < hi; e += 4) {
        int s0 = g_col[e], s1 = g_col[e + 1], s2 = g_col[e + 2], s3 = g_col[e + 3];
        float c0 = g_inv_out[s0], c1 = g_inv_out[s1];
        float c2 = g_inv_out[s2], c3 = g_inv_out[s3];
        const float4* r0 = (const float4*)(in + (size_t)s0 * ACTS);
        const float4* r1 = (const float4*)(in + (size_t)s1 * ACTS);
        const float4* r2 = (const float4*)(in + (size_t)s2 * ACTS);
        const float4* r3 = (const float4*)(in + (size_t)s3 * ACTS);
        float4 v00 = r0[lane], v10 = r1[lane], v20 = r2[lane], v30 = r3[lane];
        float4 v01, v11, v21, v31;
        if (has1) { v01 = r0[lane + 32]; v11 = r1[lane + 32];
                    v21 = r2[lane + 32]; v31 = r3[lane + 32]; }
        a0.x += v00.x * c0 + v10.x * c1 + v20.x * c2 + v30.x * c3;
        a0.y += v00.y * c0 + v10.y * c1 + v20.y * c2 + v30.y * c3;
        a0.z += v00.z * c0 + v10.z * c1 + v20.z * c2 + v30.z * c3;
        a0.w += v00.w * c0 + v10.w * c1 + v20.w * c2 + v30.w * c3;
        if (has1) {
            a1.x += v01.x * c0 + v11.x * c1 + v21.x * c2 + v31.x * c3;
            a1.y += v01.y * c0 + v11.y * c1 + v21.y * c2 + v31.y * c3;
            a1.z += v01.z * c0 + v11.z * c1 + v21.z * c2 + v31.z * c3;
            a1.w += v01.w * c0 + v11.w * c1 + v21.w * c2 + v31.w * c3;
        }
    }
    for (; e < hi; e++) {
        int s = g_col[e];
        float sc = g_inv_out[s];
        const float4* r = (const float4*)(in + (size_t)s * ACTS);
        float4 v0 = r[lane];
        a0.x += v0.x * sc; a0.y += v0.y * sc; a0.z += v0.z * sc; a0.w += v0.w * sc;
        if (has1) {
            float4 v1 = r[lane + 32];
            a1.x += v1.x * sc; a1.y += v1.y * sc; a1.z += v1.z * sc; a1.w += v1.w * sc;
        }
    }
    float oi = g_inv_in[node];
    float* orow = out + (size_t)node * 220;
    a0.x *= oi; a0.y *= oi; a0.z *= oi; a0.w *= oi;
    if (lane < 55) *(float4*)(orow + lane * 4) = a0;
    if (has1) {
        a1.x *= oi; a1.y *= oi; a1.z *= oi; a1.w *= oi;
        *(float4*)(orow + (lane + 32) * 4) = a1;
    }
}

// ---------------- tensor-core GEMM: split-bf16 (3 MMA) ----------------------
__device__ __forceinline__ void ldm_x4(uint32_t addr, uint32_t& r0, uint32_t& r1,
                                       uint32_t& r2, uint32_t& r3) {
    asm volatile("ldmatrix.sync.aligned.m8n8.x4.shared.b16 {%0,%1,%2,%3}, [%4];"
                 : "=r"(r0), "=r"(r1), "=r"(r2), "=r"(r3) : "r"(addr));
}

__device__ __forceinline__ void mma_bf16(float* c, const uint32_t* a, const uint32_t* b) {
    asm volatile(
        "mma.sync.aligned.m16n8k16.row.col.f32.bf16.bf16.f32 "
        "{%0,%1,%2,%3}, {%4,%5,%6,%7}, {%8,%9}, {%0,%1,%2,%3};"
        : "+f"(c[0]), "+f"(c[1]), "+f"(c[2]), "+f"(c[3])
        : "r"(a[0]), "r"(a[1]), "r"(a[2]), "r"(a[3]), "r"(b[0]), "r"(b[1]));
}

// C output: fp32 rows stride ACTS, tanh.approx applied. A fp32 stride K.
__global__ void k_gemm_mma_f(const float* __restrict__ A, const float* __restrict__ W,
                             const float* __restrict__ bias, float* __restrict__ C,
                             int M, int K, int N) {
    constexpr int BM = 128, BN = 128, BK = 32, LDS = BK + 8;
    __shared__ __nv_bfloat16 sAh[BM * LDS], sAl[BM * LDS];
    __shared__ __nv_bfloat16 sBh[BN * LDS], sBl[BN * LDS];

    int tid = threadIdx.x;
    int wid = tid >> 5, lane = tid & 31;
    int wm = wid >> 2, wn = wid & 3;  // 2 x 4 warps; warp tile 64x32
    int bm = blockIdx.y * BM, bn = blockIdx.x * BN;
    const bool kvec = (K % 4) == 0;

    float acc[4][4][4];
#pragma unroll
    for (int i = 0; i < 4; i++)
#pragma unroll
        for (int j = 0; j < 4; j++)
#pragma unroll
            for (int t = 0; t < 4; t++) acc[i][j][t] = 0.0f;

    uint32_t sAh_b = (uint32_t)__cvta_generic_to_shared(sAh);
    uint32_t sAl_b = (uint32_t)__cvta_generic_to_shared(sAl);
    uint32_t sBh_b = (uint32_t)__cvta_generic_to_shared(sBh);
    uint32_t sBl_b = (uint32_t)__cvta_generic_to_shared(sBl);

    for (int k0 = 0; k0 < K; k0 += BK) {
        // ---- A tile: BM x BK fp32 -> bf16 hi/lo ----
#pragma unroll
        for (int i = 0; i < 4; i++) {
            int idx = tid + i * 256;
            int row = idx >> 3;
            int c4  = idx & 7;
            int gm = bm + row;
            int kb = k0 + c4 * 4;
            float v[4] = {0.f, 0.f, 0.f, 0.f};
            if (gm < M) {
                if (kvec && kb + 3 < K) {
                    float4 f = *(const float4*)(A + (size_t)gm * K + kb);
                    v[0] = f.x; v[1] = f.y; v[2] = f.z; v[3] = f.w;
                } else {
#pragma unroll
                    for (int j = 0; j < 4; j++)
                        if (kb + j < K) v[j] = A[(size_t)gm * K + kb + j];
                }
            }
#pragma unroll
            for (int j = 0; j < 4; j++) {
                __nv_bfloat16 h = __float2bfloat16(v[j]);
                __nv_bfloat16 l = __float2bfloat16(v[j] - __bfloat162float(h));
                sAh[row * LDS + c4 * 4 + j] = h;
                sAl[row * LDS + c4 * 4 + j] = l;
            }
        }
        // ---- B tile: W[k0..k0+31][bn..bn+127], float4 along n ----
#pragma unroll
        for (int i = 0; i < 4; i++) {
            int idx = tid + i * 256;      // 0..1023
            int kk = idx >> 5;            // 0..31
            int n4 = (idx & 31) * 4;      // 0..124
            int gk = k0 + kk, gn = bn + n4;
            float v[4] = {0.f, 0.f, 0.f, 0.f};
            if (gk < K) {
                if (gn + 3 < N) {
                    float4 f = *(const float4*)(W + (size_t)gk * N + gn);
                    v[0] = f.x; v[1] = f.y; v[2] = f.z; v[3] = f.w;
                } else {
#pragma unroll
                    for (int j = 0; j < 4; j++)
                        if (gn + j < N) v[j] = W[(size_t)gk * N + gn + j];
                }
            }
#pragma unroll
            for (int j = 0; j < 4; j++) {
                __nv_bfloat16 h = __float2bfloat16(v[j]);
                __nv_bfloat16 l = __float2bfloat16(v[j] - __bfloat162float(h));
                sBh[(n4 + j) * LDS + kk] = h;
                sBl[(n4 + j) * LDS + kk] = l;
            }
        }
        __syncthreads();

        // ---- compute: 2 k-steps of 16 ----
#pragma unroll
        for (int ks = 0; ks < 2; ks++) {
            int koff = ks * 16;
            uint32_t ah[4][4], al[4][4];
#pragma unroll
            for (int mf = 0; mf < 4; mf++) {
                int r = wm * 64 + mf * 16 + (lane & 15);
                uint32_t off = (uint32_t)(r * LDS + koff + ((lane >> 4) << 3)) * 2;
                ldm_x4(sAh_b + off, ah[mf][0], ah[mf][1], ah[mf][2], ah[mf][3]);
                ldm_x4(sAl_b + off, al[mf][0], al[mf][1], al[mf][2], al[mf][3]);
            }
            uint32_t bh[4][2], bl[4][2];
#pragma unroll
            for (int nf2 = 0; nf2 < 2; nf2++) {
                int n = wn * 32 + nf2 * 16 + (lane & 7) + ((lane & 16) >> 1);
                int kl = koff + (((lane >> 3) & 1) << 3);
                uint32_t off = (uint32_t)(n * LDS + kl) * 2;
                uint32_t r0, r1, r2, r3;
                ldm_x4(sBh_b + off, r0, r1, r2, r3);
                bh[nf2 * 2][0] = r0; bh[nf2 * 2][1] = r1;
                bh[nf2 * 2 + 1][0] = r2; bh[nf2 * 2 + 1][1] = r3;
                ldm_x4(sBl_b + off, r0, r1, r2, r3);
                bl[nf2 * 2][0] = r0; bl[nf2 * 2][1] = r1;
                bl[nf2 * 2 + 1][0] = r2; bl[nf2 * 2 + 1][1] = r3;
            }
#pragma unroll
            for (int mf = 0; mf < 4; mf++)
#pragma unroll
                for (int nf = 0; nf < 4; nf++) {
                    mma_bf16(acc[mf][nf], ah[mf], bh[nf]);
                    mma_bf16(acc[mf][nf], ah[mf], bl[nf]);
                    mma_bf16(acc[mf][nf], al[mf], bh[nf]);
                }
        }
        __syncthreads();
    }

    // ---- epilogue: tanh.approx -> fp32 rows (stride ACTS), float2 stores ----
#pragma unroll
    for (int mf = 0; mf < 4; mf++) {
        int r0 = bm + wm * 64 + mf * 16 + (lane >> 2);
        int r1 = r0 + 8;
#pragma unroll
        for (int nf = 0; nf < 4; nf++) {
            int gn = bn + wn * 32 + nf * 8 + (lane & 3) * 2;  // even
            if (gn >= N) continue;
            float2 bb = make_float2(bias[gn], bias[gn + 1]);
            if (r0 < M) {
                float2 v = make_float2(tanh_fast(acc[mf][nf][0] + bb.x),
                                       tanh_fast(acc[mf][nf][1] + bb.y));
                *(float2*)(C + (size_t)r0 * ACTS + gn) = v;
            }
            if (r1 < M) {
                float2 v = make_float2(tanh_fast(acc[mf][nf][2] + bb.x),
                                       tanh_fast(acc[mf][nf][3] + bb.y));
                *(float2*)(C + (size_t)r1 * ACTS + gn) = v;
            }
        }
    }
}

// ---------------- fp32 SIMT GEMM, padded-A input (tiny layer 3) -------------
__global__ void k_gemm_f(const float* __restrict__ A, const float* __restrict__ W,
                         float* __restrict__ C, int M, int K, int N, int lda) {
    constexpr int BM = 128, BN = 64, BK = 16;
    __shared__ float As[BK][BM + 1];
    __shared__ float Bs[BK][BN];

    int bm = blockIdx.y * BM;
    int bn = blockIdx.x * BN;
    int tid = threadIdx.x;
    int tr = tid >> 4;
    int tc = tid & 15;

    float acc[8][4];
#pragma unroll
    for (int i = 0; i < 8; i++)
#pragma unroll
        for (int j = 0; j < 4; j++) acc[i][j] = 0.0f;

    for (int k0 = 0; k0 < K; k0 += BK) {
#pragma unroll
        for (int i = 0; i < 8; i++) {
            int idx = tid + i * 256;
            int m = idx >> 4;
            int kk = idx & 15;
            int gm = bm + m, gk = k0 + kk;
            float v = 0.0f;
            if (gm < M && gk < K)
                v = A[(size_t)gm * lda + gk] * g_inv_out[gm];
            As[kk][m] = v;
        }
#pragma unroll
        for (int i = 0; i < 4; i++) {
            int idx = tid + i * 256;
            int kk = idx >> 6;
            int n = idx & 63;
            int gk = k0 + kk, gn = bn + n;
            Bs[kk][n] = (gk < K && gn < N) ? W[(size_t)gk * N + gn] : 0.0f;
        }
        __syncthreads();
#pragma unroll
        for (int kk = 0; kk < BK; kk++) {
            float a[8], b[4];
#pragma unroll
            for (int i = 0; i < 8; i++) a[i] = As[kk][tr * 8 + i];
#pragma unroll
            for (int j = 0; j < 4; j++) b[j] = Bs[kk][tc * 4 + j];
#pragma unroll
            for (int i = 0; i < 8; i++)
#pragma unroll
                for (int j = 0; j < 4; j++) acc[i][j] += a[i] * b[j];
        }
        __syncthreads();
    }

#pragma unroll
    for (int i = 0; i < 8; i++) {
        int gm = bm + tr * 8 + i;
        if (gm >= M) continue;
#pragma unroll
        for (int j = 0; j < 4; j++) {
            int gn = bn + tc * 4 + j;
            if (gn >= N) continue;
            C[(size_t)gm * N + gn] = acc[i][j];
        }
    }
}

// ---------------- launch -----------------------------------------------------
extern "C" void kernel_launch(void* const* d_in, const int* in_sizes, int n_in,
                              void* d_out, int out_size) {
    const float* x  = nullptr;
    const float* W0 = nullptr; const float* W1 = nullptr;
    const float* W2 = nullptr; const float* W3 = nullptr;
    const float* b0 = nullptr; const float* b1 = nullptr;
    const float* b2 = nullptr; const float* b3 = nullptr;
    const void*  ei = nullptr;

    int n220 = 0, nbias = 0;
    for (int i = 0; i < n_in; i++) {
        int s = in_sizes[i];
        const void* p = d_in[i];
        switch (s) {
            case 1100000: x  = (const float*)p; break;
            case 4840:    W0 = (const float*)p; break;
            case 48400:   if (n220 == 0) W1 = (const float*)p;
                          else           W2 = (const float*)p;
                          n220++; break;
            case 2200:    W3 = (const float*)p; break;
            case 220:     if (nbias == 0) b0 = (const float*)p;
                          else if (nbias == 1) b1 = (const float*)p;
                          else b2 = (const float*)p;
                          nbias++; break;
            case 10:      b3 = (const float*)p; break;
            case 1600000: ei = p; break;
            default: break;
        }
    }
    float* out = (float*)d_out;

    float* bufA = nullptr; float* act = nullptr;
    if (cudaGetSymbolAddress((void**)&bufA, g_bufA) != cudaSuccess) return;
    if (cudaGetSymbolAddress((void**)&act, g_act) != cudaSuccess) return;
    if (!x || !W0 || !W1 || !W2 || !W3 || !b0 || !b1 || !b2 || !b3 || !ei) return;

    const int TB = 256;
    // graph prep
    k_detect<<<1, 32>>>((const int*)ei);
    k_convert<<<(NE + TB - 1) / TB, TB>>>(ei);
    k_init_deg<<<(NN + TB - 1) / TB, TB>>>();
    k_degrees<<<(NE + TB - 1) / TB, TB>>>();
    k_invsqrt<<<(NN + TB - 1) / TB, TB>>>();
    k_scan<<<1, 1024>>>();
    k_fill<<<(NE + TB - 1) / TB, TB>>>();

    const int AGG_BLOCKS = (NN + 7) / 8;  // 8 warps/block
    dim3 mma_grid((220 + 127) / 128, (NN + 127) / 128);
    dim3 gemm_grid3(1, (NN + 127) / 128);

    // Layer 0: agg(x fp32, F=22) -> bufA ; mma 22->220 +b0, tanh -> act
    k_aggregate<22, true, false><<<AGG_BLOCKS, TB>>>(x, bufA, nullptr);
    k_gemm_mma_f<<<mma_grid, TB>>>(bufA, W0, b0, act, NN, 22, 220);

    // Layer 1: agg fp32 padded (4-edge batched) -> bufA ; mma -> act
    k_aggregate220_f32<<<AGG_BLOCKS, TB>>>(act, bufA);
    k_gemm_mma_f<<<mma_grid, TB>>>(bufA, W1, b1, act, NN, 220, 220);

    // Layer 2
    k_aggregate220_f32<<<AGG_BLOCKS, TB>>>(act, bufA);
    k_gemm_mma_f<<<mma_grid, TB>>>(bufA, W2, b2, act, NN, 220, 220);

    // Layer 3 (reordered): z = (h*inv_out) @ W3 -> bufA[N,10]; agg 10-wide + b3
    k_gemm_f<<<gemm_grid3, TB>>>(act, W3, bufA, NN, 220, 10, ACTS);
    k_aggregate<10, false, true><<<AGG_BLOCKS, TB>>>(bufA, out, b3);
}

// round 14
// speedup vs baseline: 1.2510x; 1.2510x over previous
#include <cuda_runtime.h>
#include <cuda_fp16.h>
#include <cstdint>

#define NN 50000
#define NE 800000
#define FMAX 220
#define ACTS 224   // fp32 activation row stride (floats) = 896 B

// ---------------- scratch (static device globals; no allocation) ------------
__device__ int   g_is64;
__device__ int   g_src[NE];
__device__ int   g_dst[NE];
__device__ int   g_deg_out[NN];
__device__ int   g_deg_in[NN];
__device__ float g_inv_out[NN];
__device__ float g_inv_in[NN];
__device__ int   g_rowptr[NN + 1];
__device__ int   g_cursor[NN];
__device__ int   g_col[NE];
__device__ __align__(16) float g_bufA[(size_t)NN * FMAX];  // agg output / GEMM A (stride 220)
__device__ __align__(16) float g_act[(size_t)NN * ACTS];   // activations (stride 224)

__device__ __forceinline__ float tanh_fast(float x) {
    float y;
    asm("tanh.approx.f32 %0, %1;" : "=f"(y) : "f"(x));
    return y;
}

// ---------------- dtype detection + conversion ------------------------------
__global__ void k_detect(const int* __restrict__ ei32) {
    int lane = threadIdx.x & 31;
    int nz = (ei32[2 * lane + 1] != 0) ? 1 : 0;
    unsigned any = __ballot_sync(0xFFFFFFFFu, nz);
    if (lane == 0) g_is64 = (any == 0) ? 1 : 0;
}

__global__ void k_convert(const void* __restrict__ ei) {
    int e = blockIdx.x * blockDim.x + threadIdx.x;
    if (e >= NE) return;
    int s, d;
    if (g_is64) {
        const long long* p = (const long long*)ei;
        s = (int)p[e];
        d = (int)p[NE + e];
    } else {
        const int* p = (const int*)ei;
        s = p[e];
        d = p[NE + e];
    }
    g_src[e] = s;
    g_dst[e] = d;
}

// ---------------- graph prep ------------------------------------------------
__global__ void k_init_deg() {
    int i = blockIdx.x * blockDim.x + threadIdx.x;
    if (i < NN) { g_deg_out[i] = 0; g_deg_in[i] = 0; }
}

__global__ void k_degrees() {
    int e = blockIdx.x * blockDim.x + threadIdx.x;
    if (e < NE) {
        int s = g_src[e], d = g_dst[e];
        if ((unsigned)s < NN) atomicAdd(&g_deg_out[s], 1);
        if ((unsigned)d < NN) atomicAdd(&g_deg_in[d], 1);
    }
}

__global__ void k_invsqrt() {
    int i = blockIdx.x * blockDim.x + threadIdx.x;
    if (i < NN) {
        g_inv_out[i] = rsqrtf(fmaxf((float)g_deg_out[i], 1.0f));
        g_inv_in[i]  = rsqrtf(fmaxf((float)g_deg_in[i],  1.0f));
    }
}

__global__ void k_scan() {
    __shared__ int partial[1024];
    const int T = 1024;
    int t = threadIdx.x;
    const int chunk = (NN + T - 1) / T;
    int lo = t * chunk;
    int hi = min(lo + chunk, NN);
    int mysum = 0;
    for (int i = lo; i < hi; i++) mysum += g_deg_in[i];
    partial[t] = mysum;
    __syncthreads();
    for (int off = 1; off < T; off <<= 1) {
        int v = (t >= off) ? partial[t - off] : 0;
        __syncthreads();
        partial[t] += v;
        __syncthreads();
    }
    int run = partial[t] - mysum;
    for (int i = lo; i < hi; i++) {
        g_rowptr[i] = run;
        g_cursor[i] = run;
        run += g_deg_in[i];
    }
    if (t == 0) g_rowptr[NN] = partial[T - 1];
}

__global__ void k_fill() {
    int e = blockIdx.x * blockDim.x + threadIdx.x;
    if (e < NE) {
        int s = g_src[e];
        int d = g_dst[e];
        if ((unsigned)d < NN && (unsigned)s < NN) {
            int pos = atomicAdd(&g_cursor[d], 1);
            g_col[pos] = s;
        }
    }
}

// ---------------- aggregation (scalar fp32, F small), 4-edge batched --------
template <int F, bool SCALE_SRC, bool ADD_BIAS>
__global__ void k_aggregate(const float* __restrict__ in, float* __restrict__ out,
                            const float* __restrict__ bias) {
    int warps_per_block = blockDim.x >> 5;
    int node = blockIdx.x * warps_per_block + (threadIdx.x >> 5);
    if (node >= NN) return;
    int lane = threadIdx.x & 31;
    constexpr int J = (F + 31) / 32;
    float acc[J];
#pragma unroll
    for (int j = 0; j < J; j++) acc[j] = 0.0f;

    int lo = g_rowptr[node];
    int hi = g_rowptr[node + 1];
    int e = lo;
    for (; e + 3 < hi; e += 4) {
        int s0 = g_col[e], s1 = g_col[e + 1], s2 = g_col[e + 2], s3 = g_col[e + 3];
        float c0 = SCALE_SRC ? g_inv_out[s0] : 1.0f;
        float c1 = SCALE_SRC ? g_inv_out[s1] : 1.0f;
        float c2 = SCALE_SRC ? g_inv_out[s2] : 1.0f;
        float c3 = SCALE_SRC ? g_inv_out[s3] : 1.0f;
#pragma unroll
        for (int j = 0; j < J; j++) {
            int f = lane + 32 * j;
            if (f < F) {
                float v0 = in[(size_t)s0 * F + f];
                float v1 = in[(size_t)s1 * F + f];
                float v2 = in[(size_t)s2 * F + f];
                float v3 = in[(size_t)s3 * F + f];
                acc[j] += v0 * c0 + v1 * c1 + v2 * c2 + v3 * c3;
            }
        }
    }
    for (; e < hi; e++) {
        int s = g_col[e];
        float sc = SCALE_SRC ? g_inv_out[s] : 1.0f;
#pragma unroll
        for (int j = 0; j < J; j++) {
            int f = lane + 32 * j;
            if (f < F) acc[j] += in[(size_t)s * F + f] * sc;
        }
    }
    float oi = g_inv_in[node];
    float* orow = out + (size_t)node * F;
#pragma unroll
    for (int j = 0; j < J; j++) {
        int f = lane + 32 * j;
        if (f < F) {
            float v = acc[j] * oi;
            if (ADD_BIAS) v += bias[f];
            orow[f] = v;
        }
    }
}

// ---------------- aggregation F=220 fp32 padded rows, 4-edge batched --------
__global__ void k_aggregate220_f32(const float* __restrict__ in,
                                   float* __restrict__ out) {
    int warps_per_block = blockDim.x >> 5;
    int node = blockIdx.x * warps_per_block + (threadIdx.x >> 5);
    if (node >= NN) return;
    int lane = threadIdx.x & 31;
    bool has1 = (lane + 32) < 55;

    float4 a0 = make_float4(0.f, 0.f, 0.f, 0.f);
    float4 a1 = make_float4(0.f, 0.f, 0.f, 0.f);

    int lo = g_rowptr[node];
    int hi = g_rowptr[node + 1];
    int e = lo;
    for (; e + 3 < hi; e += 4) {
        int s0 = g_col[e], s1 = g_col[e + 1], s2 = g_col[e + 2], s3 = g_col[e + 3];
        float c0 = g_inv_out[s0], c1 = g_inv_out[s1];
        float c2 = g_inv_out[s2], c3 = g_inv_out[s3];
        const float4* r0 = (const float4*)(in + (size_t)s0 * ACTS);
        const float4* r1 = (const float4*)(in + (size_t)s1 * ACTS);
        const float4* r2 = (const float4*)(in + (size_t)s2 * ACTS);
        const float4* r3 = (const float4*)(in + (size_t)s3 * ACTS);
        float4 v00 = r0[lane], v10 = r1[lane], v20 = r2[lane], v30 = r3[lane];
        float4 v01, v11, v21, v31;
        if (has1) { v01 = r0[lane + 32]; v11 = r1[lane + 32];
                    v21 = r2[lane + 32]; v31 = r3[lane + 32]; }
        a0.x += v00.x * c0 + v10.x * c1 + v20.x * c2 + v30.x * c3;
        a0.y += v00.y * c0 + v10.y * c1 + v20.y * c2 + v30.y * c3;
        a0.z += v00.z * c0 + v10.z * c1 + v20.z * c2 + v30.z * c3;
        a0.w += v00.w * c0 + v10.w * c1 + v20.w * c2 + v30.w * c3;
        if (has1) {
            a1.x += v01.x * c0 + v11.x * c1 + v21.x * c2 + v31.x * c3;
            a1.y += v01.y * c0 + v11.y * c1 + v21.y * c2 + v31.y * c3;
            a1.z += v01.z * c0 + v11.z * c1 + v21.z * c2 + v31.z * c3;
            a1.w += v01.w * c0 + v11.w * c1 + v21.w * c2 + v31.w * c3;
        }
    }
    for (; e < hi; e++) {
        int s = g_col[e];
        float sc = g_inv_out[s];
        const float4* r = (const float4*)(in + (size_t)s * ACTS);
        float4 v0 = r[lane];
        a0.x += v0.x * sc; a0.y += v0.y * sc; a0.z += v0.z * sc; a0.w += v0.w * sc;
        if (has1) {
            float4 v1 = r[lane + 32];
            a1.x += v1.x * sc; a1.y += v1.y * sc; a1.z += v1.z * sc; a1.w += v1.w * sc;
        }
    }
    float oi = g_inv_in[node];
    float* orow = out + (size_t)node * 220;
    a0.x *= oi; a0.y *= oi; a0.z *= oi; a0.w *= oi;
    if (lane < 55) *(float4*)(orow + lane * 4) = a0;
    if (has1) {
        a1.x *= oi; a1.y *= oi; a1.z *= oi; a1.w *= oi;
        *(float4*)(orow + (lane + 32) * 4) = a1;
    }
}

// ---------------- tensor-core GEMM: single fp16 MMA -------------------------
__device__ __forceinline__ void ldm_x4(uint32_t addr, uint32_t& r0, uint32_t& r1,
                                       uint32_t& r2, uint32_t& r3) {
    asm volatile("ldmatrix.sync.aligned.m8n8.x4.shared.b16 {%0,%1,%2,%3}, [%4];"
                 : "=r"(r0), "=r"(r1), "=r"(r2), "=r"(r3) : "r"(addr));
}

__device__ __forceinline__ void mma_f16(float* c, const uint32_t* a, const uint32_t* b) {
    asm volatile(
        "mma.sync.aligned.m16n8k16.row.col.f32.f16.f16.f32 "
        "{%0,%1,%2,%3}, {%4,%5,%6,%7}, {%8,%9}, {%0,%1,%2,%3};"
        : "+f"(c[0]), "+f"(c[1]), "+f"(c[2]), "+f"(c[3])
        : "r"(a[0]), "r"(a[1]), "r"(a[2]), "r"(a[3]), "r"(b[0]), "r"(b[1]));
}

// C output: fp32 rows stride ACTS, tanh.approx applied. A fp32 stride K.
__global__ void k_gemm_mma_f(const float* __restrict__ A, const float* __restrict__ W,
                             const float* __restrict__ bias, float* __restrict__ C,
                             int M, int K, int N) {
    constexpr int BM = 128, BN = 128, BK = 32, LDS = BK + 8;
    __shared__ __half sA[BM * LDS];
    __shared__ __half sB[BN * LDS];

    int tid = threadIdx.x;
    int wid = tid >> 5, lane = tid & 31;
    int wm = wid >> 2, wn = wid & 3;  // 2 x 4 warps; warp tile 64x32
    int bm = blockIdx.y * BM, bn = blockIdx.x * BN;
    const bool kvec = (K % 4) == 0;

    float acc[4][4][4];
#pragma unroll
    for (int i = 0; i < 4; i++)
#pragma unroll
        for (int j = 0; j < 4; j++)
#pragma unroll
            for (int t = 0; t < 4; t++) acc[i][j][t] = 0.0f;

    uint32_t sA_b = (uint32_t)__cvta_generic_to_shared(sA);
    uint32_t sB_b = (uint32_t)__cvta_generic_to_shared(sB);

    for (int k0 = 0; k0 < K; k0 += BK) {
        // ---- A tile: BM x BK fp32 -> fp16 ----
#pragma unroll
        for (int i = 0; i < 4; i++) {
            int idx = tid + i * 256;
            int row = idx >> 3;
            int c4  = idx & 7;
            int gm = bm + row;
            int kb = k0 + c4 * 4;
            float v[4] = {0.f, 0.f, 0.f, 0.f};
            if (gm < M) {
                if (kvec && kb + 3 < K) {
                    float4 f = *(const float4*)(A + (size_t)gm * K + kb);
                    v[0] = f.x; v[1] = f.y; v[2] = f.z; v[3] = f.w;
                } else {
#pragma unroll
                    for (int j = 0; j < 4; j++)
                        if (kb + j < K) v[j] = A[(size_t)gm * K + kb + j];
                }
            }
#pragma unroll
            for (int j = 0; j < 4; j++)
                sA[row * LDS + c4 * 4 + j] = __float2half_rn(v[j]);
        }
        // ---- B tile: W[k0..k0+31][bn..bn+127], float4 along n ----
#pragma unroll
        for (int i = 0; i < 4; i++) {
            int idx = tid + i * 256;      // 0..1023
            int kk = idx >> 5;            // 0..31
            int n4 = (idx & 31) * 4;      // 0..124
            int gk = k0 + kk, gn = bn + n4;
            float v[4] = {0.f, 0.f, 0.f, 0.f};
            if (gk < K) {
                if (gn + 3 < N) {
                    float4 f = *(const float4*)(W + (size_t)gk * N + gn);
                    v[0] = f.x; v[1] = f.y; v[2] = f.z; v[3] = f.w;
                } else {
#pragma unroll
                    for (int j = 0; j < 4; j++)
                        if (gn + j < N) v[j] = W[(size_t)gk * N + gn + j];
                }
            }
#pragma unroll
            for (int j = 0; j < 4; j++)
                sB[(n4 + j) * LDS + kk] = __float2half_rn(v[j]);
        }
        __syncthreads();

        // ---- compute: 2 k-steps of 16 ----
#pragma unroll
        for (int ks = 0; ks < 2; ks++) {
            int koff = ks * 16;
            uint32_t a[4][4];
#pragma unroll
            for (int mf = 0; mf < 4; mf++) {
                int r = wm * 64 + mf * 16 + (lane & 15);
                uint32_t off = (uint32_t)(r * LDS + koff + ((lane >> 4) << 3)) * 2;
                ldm_x4(sA_b + off, a[mf][0], a[mf][1], a[mf][2], a[mf][3]);
            }
            uint32_t b[4][2];
#pragma unroll
            for (int nf2 = 0; nf2 < 2; nf2++) {
                int n = wn * 32 + nf2 * 16 + (lane & 7) + ((lane & 16) >> 1);
                int kl = koff + (((lane >> 3) & 1) << 3);
                uint32_t off = (uint32_t)(n * LDS + kl) * 2;
                uint32_t r0, r1, r2, r3;
                ldm_x4(sB_b + off, r0, r1, r2, r3);
                b[nf2 * 2][0] = r0; b[nf2 * 2][1] = r1;
                b[nf2 * 2 + 1][0] = r2; b[nf2 * 2 + 1][1] = r3;
            }
#pragma unroll
            for (int mf = 0; mf < 4; mf++)
#pragma unroll
                for (int nf = 0; nf < 4; nf++)
                    mma_f16(acc[mf][nf], a[mf], b[nf]);
        }
        __syncthreads();
    }

    // ---- epilogue: tanh.approx -> fp32 rows (stride ACTS), float2 stores ----
#pragma unroll
    for (int mf = 0; mf < 4; mf++) {
        int r0 = bm + wm * 64 + mf * 16 + (lane >> 2);
        int r1 = r0 + 8;
#pragma unroll
        for (int nf = 0; nf < 4; nf++) {
            int gn = bn + wn * 32 + nf * 8 + (lane & 3) * 2;  // even
            if (gn >= N) continue;
            float2 bb = make_float2(bias[gn], bias[gn + 1]);
            if (r0 < M) {
                float2 v = make_float2(tanh_fast(acc[mf][nf][0] + bb.x),
                                       tanh_fast(acc[mf][nf][1] + bb.y));
                *(float2*)(C + (size_t)r0 * ACTS + gn) = v;
            }
            if (r1 < M) {
                float2 v = make_float2(tanh_fast(acc[mf][nf][2] + bb.x),
                                       tanh_fast(acc[mf][nf][3] + bb.y));
                *(float2*)(C + (size_t)r1 * ACTS + gn) = v;
            }
        }
    }
}

// ---------------- fp32 SIMT GEMM, padded-A input (tiny layer 3) -------------
__global__ void k_gemm_f(const float* __restrict__ A, const float* __restrict__ W,
                         float* __restrict__ C, int M, int K, int N, int lda) {
    constexpr int BM = 128, BN = 64, BK = 16;
    __shared__ float As[BK][BM + 1];
    __shared__ float Bs[BK][BN];

    int bm = blockIdx.y * BM;
    int bn = blockIdx.x * BN;
    int tid = threadIdx.x;
    int tr = tid >> 4;
    int tc = tid & 15;

    float acc[8][4];
#pragma unroll
    for (int i = 0; i < 8; i++)
#pragma unroll
        for (int j = 0; j < 4; j++) acc[i][j] = 0.0f;

    for (int k0 = 0; k0 < K; k0 += BK) {
#pragma unroll
        for (int i = 0; i < 8; i++) {
            int idx = tid + i * 256;
            int m = idx >> 4;
            int kk = idx & 15;
            int gm = bm + m, gk = k0 + kk;
            float v = 0.0f;
            if (gm < M && gk < K)
                v = A[(size_t)gm * lda + gk] * g_inv_out[gm];
            As[kk][m] = v;
        }
#pragma unroll
        for (int i = 0; i < 4; i++) {
            int idx = tid + i * 256;
            int kk = idx >> 6;
            int n = idx & 63;
            int gk = k0 + kk, gn = bn + n;
            Bs[kk][n] = (gk < K && gn < N) ? W[(size_t)gk * N + gn] : 0.0f;
        }
        __syncthreads();
#pragma unroll
        for (int kk = 0; kk < BK; kk++) {
            float a[8], b[4];
#pragma unroll
            for (int i = 0; i < 8; i++) a[i] = As[kk][tr * 8 + i];
#pragma unroll
            for (int j = 0; j < 4; j++) b[j] = Bs[kk][tc * 4 + j];
#pragma unroll
            for (int i = 0; i < 8; i++)
#pragma unroll
                for (int j = 0; j < 4; j++) acc[i][j] += a[i] * b[j];
        }
        __syncthreads();
    }

#pragma unroll
    for (int i = 0; i < 8; i++) {
        int gm = bm + tr * 8 + i;
        if (gm >= M) continue;
#pragma unroll
        for (int j = 0; j < 4; j++) {
            int gn = bn + tc * 4 + j;
            if (gn >= N) continue;
            C[(size_t)gm * N + gn] = acc[i][j];
        }
    }
}

// ---------------- launch -----------------------------------------------------
extern "C" void kernel_launch(void* const* d_in, const int* in_sizes, int n_in,
                              void* d_out, int out_size) {
    const float* x  = nullptr;
    const float* W0 = nullptr; const float* W1 = nullptr;
    const float* W2 = nullptr; const float* W3 = nullptr;
    const float* b0 = nullptr; const float* b1 = nullptr;
    const float* b2 = nullptr; const float* b3 = nullptr;
    const void*  ei = nullptr;

    int n220 = 0, nbias = 0;
    for (int i = 0; i < n_in; i++) {
        int s = in_sizes[i];
        const void* p = d_in[i];
        switch (s) {
            case 1100000: x  = (const float*)p; break;
            case 4840:    W0 = (const float*)p; break;
            case 48400:   if (n220 == 0) W1 = (const float*)p;
                          else           W2 = (const float*)p;
                          n220++; break;
            case 2200:    W3 = (const float*)p; break;
            case 220:     if (nbias == 0) b0 = (const float*)p;
                          else if (nbias == 1) b1 = (const float*)p;
                          else b2 = (const float*)p;
                          nbias++; break;
            case 10:      b3 = (const float*)p; break;
            case 1600000: ei = p; break;
            default: break;
        }
    }
    float* out = (float*)d_out;

    float* bufA = nullptr; float* act = nullptr;
    if (cudaGetSymbolAddress((void**)&bufA, g_bufA) != cudaSuccess) return;
    if (cudaGetSymbolAddress((void**)&act, g_act) != cudaSuccess) return;
    if (!x || !W0 || !W1 || !W2 || !W3 || !b0 || !b1 || !b2 || !b3 || !ei) return;

    const int TB = 256;
    // graph prep
    k_detect<<<1, 32>>>((const int*)ei);
    k_convert<<<(NE + TB - 1) / TB, TB>>>(ei);
    k_init_deg<<<(NN + TB - 1) / TB, TB>>>();
    k_degrees<<<(NE + TB - 1) / TB, TB>>>();
    k_invsqrt<<<(NN + TB - 1) / TB, TB>>>();
    k_scan<<<1, 1024>>>();
    k_fill<<<(NE + TB - 1) / TB, TB>>>();

    const int AGG_BLOCKS = (NN + 7) / 8;  // 8 warps/block
    dim3 mma_grid((220 + 127) / 128, (NN + 127) / 128);
    dim3 gemm_grid3(1, (NN + 127) / 128);

    // Layer 0: agg(x fp32, F=22) -> bufA ; mma 22->220 +b0, tanh -> act
    k_aggregate<22, true, false><<<AGG_BLOCKS, TB>>>(x, bufA, nullptr);
    k_gemm_mma_f<<<mma_grid, TB>>>(bufA, W0, b0, act, NN, 22, 220);

    // Layer 1: agg fp32 padded (4-edge batched) -> bufA ; mma -> act
    k_aggregate220_f32<<<AGG_BLOCKS, TB>>>(act, bufA);
    k_gemm_mma_f<<<mma_grid, TB>>>(bufA, W1, b1, act, NN, 220, 220);

    // Layer 2
    k_aggregate220_f32<<<AGG_BLOCKS, TB>>>(act, bufA);
    k_gemm_mma_f<<<mma_grid, TB>>>(bufA, W2, b2, act, NN, 220, 220);

    // Layer 3 (reordered): z = (h*inv_out) @ W3 -> bufA[N,10]; agg 10-wide + b3
    k_gemm_f<<<gemm_grid3, TB>>>(act, W3, bufA, NN, 220, 10, ACTS);
    k_aggregate<10, false, true><<<AGG_BLOCKS, TB>>>(bufA, out, b3);
}

// round 17
// speedup vs baseline: 1.6718x; 1.3365x over previous
#include <cuda_runtime.h>
#include <cuda_fp16.h>
#include <cstdint>

#define NN 50000
#define NNP 50048   // NN padded to multiple of 128 (BM) for unguarded loads
#define NE 800000
#define ACTS 224    // fp32 activation row stride (floats)
#define A16S 224    // fp16 GEMM-A row stride (halves) layers 1/2
#define A16S0 32    // fp16 GEMM-A row stride (halves) layer 0 (K=22 + pad)
#define WTS 224     // fp16 WT row stride (halves)

// ---------------- scratch (static device globals; no allocation) ------------
__device__ int   g_is64;
__device__ int   g_src[NE];
__device__ int   g_dst[NE];
__device__ int   g_deg_out[NN];
__device__ int   g_deg_in[NN];
__device__ float g_inv_out[NN];
__device__ float g_inv_in[NN];
__device__ int   g_rowptr[NN + 1];
__device__ int   g_cursor[NN];
__device__ int   g_col[NE];
__device__ __align__(16) float  g_bufA[(size_t)NN * 10];      // layer3 z
__device__ __align__(16) float  g_act[(size_t)NNP * ACTS];    // fp32 activations
__device__ __align__(16) __half g_a16[(size_t)NNP * A16S];    // fp16 GEMM A (layers 1/2)
__device__ __align__(16) __half g_a16s[(size_t)NNP * A16S0];  // fp16 GEMM A (layer 0)
__device__ __align__(16) __half g_wt16[(size_t)256 * WTS];    // fp16 W^T (n-major)

__device__ __forceinline__ float tanh_fast(float x) {
    float y;
    asm("tanh.approx.f32 %0, %1;" : "=f"(y) : "f"(x));
    return y;
}

// ---------------- dtype detection + conversion ------------------------------
__global__ void k_detect(const int* __restrict__ ei32) {
    int lane = threadIdx.x & 31;
    int nz = (ei32[2 * lane + 1] != 0) ? 1 : 0;
    unsigned any = __ballot_sync(0xFFFFFFFFu, nz);
    if (lane == 0) g_is64 = (any == 0) ? 1 : 0;
}

__global__ void k_convert(const void* __restrict__ ei) {
    int e = blockIdx.x * blockDim.x + threadIdx.x;
    if (e >= NE) return;
    int s, d;
    if (g_is64) {
        const long long* p = (const long long*)ei;
        s = (int)p[e];
        d = (int)p[NE + e];
    } else {
        const int* p = (const int*)ei;
        s = p[e];
        d = p[NE + e];
    }
    g_src[e] = s;
    g_dst[e] = d;
}

// ---------------- graph prep ------------------------------------------------
__global__ void k_init_deg() {
    int i = blockIdx.x * blockDim.x + threadIdx.x;
    if (i < NN) { g_deg_out[i] = 0; g_deg_in[i] = 0; }
}

__global__ void k_degrees() {
    int e = blockIdx.x * blockDim.x + threadIdx.x;
    if (e < NE) {
        int s = g_src[e], d = g_dst[e];
        if ((unsigned)s < NN) atomicAdd(&g_deg_out[s], 1);
        if ((unsigned)d < NN) atomicAdd(&g_deg_in[d], 1);
    }
}

__global__ void k_invsqrt() {
    int i = blockIdx.x * blockDim.x + threadIdx.x;
    if (i < NN) {
        g_inv_out[i] = rsqrtf(fmaxf((float)g_deg_out[i], 1.0f));
        g_inv_in[i]  = rsqrtf(fmaxf((float)g_deg_in[i],  1.0f));
    }
}

__global__ void k_scan() {
    __shared__ int partial[1024];
    const int T = 1024;
    int t = threadIdx.x;
    const int chunk = (NN + T - 1) / T;
    int lo = t * chunk;
    int hi = min(lo + chunk, NN);
    int mysum = 0;
    for (int i = lo; i < hi; i++) mysum += g_deg_in[i];
    partial[t] = mysum;
    __syncthreads();
    for (int off = 1; off < T; off <<= 1) {
        int v = (t >= off) ? partial[t - off] : 0;
        __syncthreads();
        partial[t] += v;
        __syncthreads();
    }
    int run = partial[t] - mysum;
    for (int i = lo; i < hi; i++) {
        g_rowptr[i] = run;
        g_cursor[i] = run;
        run += g_deg_in[i];
    }
    if (t == 0) g_rowptr[NN] = partial[T - 1];
}

__global__ void k_fill() {
    int e = blockIdx.x * blockDim.x + threadIdx.x;
    if (e < NE) {
        int s = g_src[e];
        int d = g_dst[e];
        if ((unsigned)d < NN && (unsigned)s < NN) {
            int pos = atomicAdd(&g_cursor[d], 1);
            g_col[pos] = s;
        }
    }
}

// ---------------- W transpose + fp16 convert --------------------------------
// WT[n*ldk + k] = (n<N && k<K) ? W[k*N + n] : 0 ; writes ALL 256*ldk cells.
__global__ void k_wt16(const float* __restrict__ W, __half* __restrict__ WT,
                       int K, int N, int ldk) {
    int idx = blockIdx.x * blockDim.x + threadIdx.x;
    if (idx >= 256 * ldk) return;
    int n = idx / ldk, k = idx % ldk;
    float v = (n < N && k < K) ? W[(size_t)k * N + n] : 0.0f;
    WT[idx] = __float2half_rn(v);
}

// ---------------- aggregation (fp32 out, F small), 4-edge batched -----------
template <int F, bool SCALE_SRC, bool ADD_BIAS>
__global__ void k_aggregate(const float* __restrict__ in, float* __restrict__ out,
                            const float* __restrict__ bias) {
    int warps_per_block = blockDim.x >> 5;
    int node = blockIdx.x * warps_per_block + (threadIdx.x >> 5);
    if (node >= NN) return;
    int lane = threadIdx.x & 31;
    constexpr int J = (F + 31) / 32;
    float acc[J];
#pragma unroll
    for (int j = 0; j < J; j++) acc[j] = 0.0f;

    int lo = g_rowptr[node];
    int hi = g_rowptr[node + 1];
    int e = lo;
    for (; e + 3 < hi; e += 4) {
        int s0 = g_col[e], s1 = g_col[e + 1], s2 = g_col[e + 2], s3 = g_col[e + 3];
        float c0 = SCALE_SRC ? g_inv_out[s0] : 1.0f;
        float c1 = SCALE_SRC ? g_inv_out[s1] : 1.0f;
        float c2 = SCALE_SRC ? g_inv_out[s2] : 1.0f;
        float c3 = SCALE_SRC ? g_inv_out[s3] : 1.0f;
#pragma unroll
        for (int j = 0; j < J; j++) {
            int f = lane + 32 * j;
            if (f < F) {
                acc[j] += in[(size_t)s0 * F + f] * c0 + in[(size_t)s1 * F + f] * c1
                        + in[(size_t)s2 * F + f] * c2 + in[(size_t)s3 * F + f] * c3;
            }
        }
    }
    for (; e < hi; e++) {
        int s = g_col[e];
        float sc = SCALE_SRC ? g_inv_out[s] : 1.0f;
#pragma unroll
        for (int j = 0; j < J; j++) {
            int f = lane + 32 * j;
            if (f < F) acc[j] += in[(size_t)s * F + f] * sc;
        }
    }
    float oi = g_inv_in[node];
    float* orow = out + (size_t)node * F;
#pragma unroll
    for (int j = 0; j < J; j++) {
        int f = lane + 32 * j;
        if (f < F) {
            float v = acc[j] * oi;
            if (ADD_BIAS) v += bias[f];
            orow[f] = v;
        }
    }
}

// ---------------- layer-0 aggregation: x fp32 -> fp16 rows stride 32 --------
__global__ void k_aggregate22_h(const float* __restrict__ in, __half* __restrict__ out) {
    int warps_per_block = blockDim.x >> 5;
    int node = blockIdx.x * warps_per_block + (threadIdx.x >> 5);
    if (node >= NN) return;
    int lane = threadIdx.x & 31;
    float acc = 0.0f;

    int lo = g_rowptr[node];
    int hi = g_rowptr[node + 1];
    int e = lo;
    for (; e + 3 < hi; e += 4) {
        int s0 = g_col[e], s1 = g_col[e + 1], s2 = g_col[e + 2], s3 = g_col[e + 3];
        float c0 = g_inv_out[s0], c1 = g_inv_out[s1];
        float c2 = g_inv_out[s2], c3 = g_inv_out[s3];
        if (lane < 22) {
            acc += in[(size_t)s0 * 22 + lane] * c0 + in[(size_t)s1 * 22 + lane] * c1
                 + in[(size_t)s2 * 22 + lane] * c2 + in[(size_t)s3 * 22 + lane] * c3;
        }
    }
    for (; e < hi; e++) {
        int s = g_col[e];
        float sc = g_inv_out[s];
        if (lane < 22) acc += in[(size_t)s * 22 + lane] * sc;
    }
    if (lane < 22)
        out[(size_t)node * A16S0 + lane] = __float2half_rn(acc * g_inv_in[node]);
}

// ---------------- aggregation F=220 fp32 in -> fp16 out, 4-edge batched -----
// FIXED store mapping: a0 holds features lane*4..+3 -> halves lane*4;
// a1 holds features (lane+32)*4..+3 -> halves (lane+32)*4 (lane<23).
__global__ void k_aggregate220_f32h(const float* __restrict__ in,
                                    __half* __restrict__ out) {
    int warps_per_block = blockDim.x >> 5;
    int node = blockIdx.x * warps_per_block + (threadIdx.x >> 5);
    if (node >= NN) return;
    int lane = threadIdx.x & 31;
    bool has1 = (lane + 32) < 55;

    float4 a0 = make_float4(0.f, 0.f, 0.f, 0.f);
    float4 a1 = make_float4(0.f, 0.f, 0.f, 0.f);

    int lo = g_rowptr[node];
    int hi = g_rowptr[node + 1];
    int e = lo;
    for (; e + 3 < hi; e += 4) {
        int s0 = g_col[e], s1 = g_col[e + 1], s2 = g_col[e + 2], s3 = g_col[e + 3];
        float c0 = g_inv_out[s0], c1 = g_inv_out[s1];
        float c2 = g_inv_out[s2], c3 = g_inv_out[s3];
        const float4* r0 = (const float4*)(in + (size_t)s0 * ACTS);
        const float4* r1 = (const float4*)(in + (size_t)s1 * ACTS);
        const float4* r2 = (const float4*)(in + (size_t)s2 * ACTS);
        const float4* r3 = (const float4*)(in + (size_t)s3 * ACTS);
        float4 v00 = r0[lane], v10 = r1[lane], v20 = r2[lane], v30 = r3[lane];
        float4 v01, v11, v21, v31;
        if (has1) { v01 = r0[lane + 32]; v11 = r1[lane + 32];
                    v21 = r2[lane + 32]; v31 = r3[lane + 32]; }
        a0.x += v00.x * c0 + v10.x * c1 + v20.x * c2 + v30.x * c3;
        a0.y += v00.y * c0 + v10.y * c1 + v20.y * c2 + v30.y * c3;
        a0.z += v00.z * c0 + v10.z * c1 + v20.z * c2 + v30.z * c3;
        a0.w += v00.w * c0 + v10.w * c1 + v20.w * c2 + v30.w * c3;
        if (has1) {
            a1.x += v01.x * c0 + v11.x * c1 + v21.x * c2 + v31.x * c3;
            a1.y += v01.y * c0 + v11.y * c1 + v21.y * c2 + v31.y * c3;
            a1.z += v01.z * c0 + v11.z * c1 + v21.z * c2 + v31.z * c3;
            a1.w += v01.w * c0 + v11.w * c1 + v21.w * c2 + v31.w * c3;
        }
    }
    for (; e < hi; e++) {
        int s = g_col[e];
        float sc = g_inv_out[s];
        const float4* r = (const float4*)(in + (size_t)s * ACTS);
        float4 v0 = r[lane];
        a0.x += v0.x * sc; a0.y += v0.y * sc; a0.z += v0.z * sc; a0.w += v0.w * sc;
        if (has1) {
            float4 v1 = r[lane + 32];
            a1.x += v1.x * sc; a1.y += v1.y * sc; a1.z += v1.z * sc; a1.w += v1.w * sc;
        }
    }
    float oi = g_inv_in[node];
    __half* orow = out + (size_t)node * A16S;
    {
        __half2 p0 = __floats2half2_rn(a0.x * oi, a0.y * oi);
        __half2 p1 = __floats2half2_rn(a0.z * oi, a0.w * oi);
        uint2 pk;
        pk.x = *(uint32_t*)&p0; pk.y = *(uint32_t*)&p1;
        *(uint2*)(orow + lane * 4) = pk;            // features lane*4 .. +3
    }
    if (has1) {
        __half2 p0 = __floats2half2_rn(a1.x * oi, a1.y * oi);
        __half2 p1 = __floats2half2_rn(a1.z * oi, a1.w * oi);
        uint2 pk;
        pk.x = *(uint32_t*)&p0; pk.y = *(uint32_t*)&p1;
        *(uint2*)(orow + (lane + 32) * 4) = pk;     // features lane*4+128 .. +131
    }
}

// ---------------- tensor-core GEMM: fp16 in, ping-pong smem -----------------
__device__ __forceinline__ void ldm_x4(uint32_t addr, uint32_t& r0, uint32_t& r1,
                                       uint32_t& r2, uint32_t& r3) {
    asm volatile("ldmatrix.sync.aligned.m8n8.x4.shared.b16 {%0,%1,%2,%3}, [%4];"
                 : "=r"(r0), "=r"(r1), "=r"(r2), "=r"(r3) : "r"(addr));
}

__device__ __forceinline__ void mma_f16(float* c, const uint32_t* a, const uint32_t* b) {
    asm volatile(
        "mma.sync.aligned.m16n8k16.row.col.f32.f16.f16.f32 "
        "{%0,%1,%2,%3}, {%4,%5,%6,%7}, {%8,%9}, {%0,%1,%2,%3};"
        : "+f"(c[0]), "+f"(c[1]), "+f"(c[2]), "+f"(c[3])
        : "r"(a[0]), "r"(a[1]), "r"(a[2]), "r"(a[3]), "r"(b[0]), "r"(b[1]));
}

// A: fp16 rows stride ld (zero-padded, NNP rows). B: WT16 fp16 [256][ld].
// C: fp32 rows stride ACTS, tanh.approx + bias. K_eff multiple of 32.
__global__ void k_gemm_mma_h16(const __half* __restrict__ A,
                               const __half* __restrict__ B,
                               const float* __restrict__ bias,
                               float* __restrict__ C,
                               int M, int N, int K_eff, int ld) {
    constexpr int BM = 128, BN = 128, BK = 32, LDS = BK + 8;
    __shared__ __half sA[2][BM * LDS];
    __shared__ __half sB[2][BN * LDS];

    int tid = threadIdx.x;
    int wid = tid >> 5, lane = tid & 31;
    int wm = wid >> 2, wn = wid & 3;  // 2 x 4 warps; warp tile 64x32
    int bm = blockIdx.y * BM, bn = blockIdx.x * BN;

    float acc[4][4][4];
#pragma unroll
    for (int i = 0; i < 4; i++)
#pragma unroll
        for (int j = 0; j < 4; j++)
#pragma unroll
            for (int t = 0; t < 4; t++) acc[i][j][t] = 0.0f;

    uint32_t sA0 = (uint32_t)__cvta_generic_to_shared(&sA[0][0]);
    uint32_t sB0 = (uint32_t)__cvta_generic_to_shared(&sB[0][0]);
    const uint32_t bufBytes = BM * LDS * 2;

    int row = tid >> 2;            // 0..63 (+64 on second pass)
    int g8  = (tid & 3) * 8;       // 0,8,16,24

    auto load_tiles = [&](int buf, int k0) {
#pragma unroll
        for (int i = 0; i < 2; i++) {
            int r = row + i * 64;
            uint4 va = *(const uint4*)(A + (size_t)(bm + r) * ld + k0 + g8);
            *(uint4*)(&sA[buf][r * LDS + g8]) = va;
            uint4 vb = *(const uint4*)(B + (size_t)(bn + r) * ld + k0 + g8);
            *(uint4*)(&sB[buf][r * LDS + g8]) = vb;
        }
    };

    int nIter = K_eff >> 5;
    load_tiles(0, 0);
    __syncthreads();

    for (int it = 0; it < nIter; it++) {
        if (it + 1 < nIter) load_tiles((it + 1) & 1, (it + 1) * BK);
        uint32_t sAb = sA0 + (uint32_t)(it & 1) * bufBytes;
        uint32_t sBb = sB0 + (uint32_t)(it & 1) * bufBytes;
#pragma unroll
        for (int ks = 0; ks < 2; ks++) {
            int koff = ks * 16;
            uint32_t a[4][4];
#pragma unroll
            for (int mf = 0; mf < 4; mf++) {
                int r = wm * 64 + mf * 16 + (lane & 15);
                uint32_t off = (uint32_t)(r * LDS + koff + ((lane >> 4) << 3)) * 2;
                ldm_x4(sAb + off, a[mf][0], a[mf][1], a[mf][2], a[mf][3]);
            }
            uint32_t b[4][2];
#pragma unroll
            for (int nf2 = 0; nf2 < 2; nf2++) {
                int n = wn * 32 + nf2 * 16 + (lane & 7) + ((lane & 16) >> 1);
                int kl = koff + (((lane >> 3) & 1) << 3);
                uint32_t off = (uint32_t)(n * LDS + kl) * 2;
                uint32_t r0, r1, r2, r3;
                ldm_x4(sBb + off, r0, r1, r2, r3);
                b[nf2 * 2][0] = r0; b[nf2 * 2][1] = r1;
                b[nf2 * 2 + 1][0] = r2; b[nf2 * 2 + 1][1] = r3;
            }
#pragma unroll
            for (int mf = 0; mf < 4; mf++)
#pragma unroll
                for (int nf = 0; nf < 4; nf++)
                    mma_f16(acc[mf][nf], a[mf], b[nf]);
        }
        __syncthreads();
    }

    // ---- epilogue: tanh.approx -> fp32 rows (stride ACTS), float2 stores ----
#pragma unroll
    for (int mf = 0; mf < 4; mf++) {
        int r0 = bm + wm * 64 + mf * 16 + (lane >> 2);
        int r1 = r0 + 8;
#pragma unroll
        for (int nf = 0; nf < 4; nf++) {
            int gn = bn + wn * 32 + nf * 8 + (lane & 3) * 2;
            if (gn >= N) continue;
            float2 bb = make_float2(bias[gn], bias[gn + 1]);
            if (r0 < M) {
                float2 v = make_float2(tanh_fast(acc[mf][nf][0] + bb.x),
                                       tanh_fast(acc[mf][nf][1] + bb.y));
                *(float2*)(C + (size_t)r0 * ACTS + gn) = v;
            }
            if (r1 < M) {
                float2 v = make_float2(tanh_fast(acc[mf][nf][2] + bb.x),
                                       tanh_fast(acc[mf][nf][3] + bb.y));
                *(float2*)(C + (size_t)r1 * ACTS + gn) = v;
            }
        }
    }
}

// ---------------- fp32 SIMT GEMM, padded-A input (tiny layer 3) -------------
__global__ void k_gemm_f(const float* __restrict__ A, const float* __restrict__ W,
                         float* __restrict__ C, int M, int K, int N, int lda) {
    constexpr int BM = 128, BN = 64, BK = 16;
    __shared__ float As[BK][BM + 1];
    __shared__ float Bs[BK][BN];

    int bm = blockIdx.y * BM;
    int bn = blockIdx.x * BN;
    int tid = threadIdx.x;
    int tr = tid >> 4;
    int tc = tid & 15;

    float acc[8][4];
#pragma unroll
    for (int i = 0; i < 8; i++)
#pragma unroll
        for (int j = 0; j < 4; j++) acc[i][j] = 0.0f;

    for (int k0 = 0; k0 < K; k0 += BK) {
#pragma unroll
        for (int i = 0; i < 8; i++) {
            int idx = tid + i * 256;
            int m = idx >> 4;
            int kk = idx & 15;
            int gm = bm + m, gk = k0 + kk;
            float v = 0.0f;
            if (gm < M && gk < K)
                v = A[(size_t)gm * lda + gk] * g_inv_out[gm];
            As[kk][m] = v;
        }
#pragma unroll
        for (int i = 0; i < 4; i++) {
            int idx = tid + i * 256;
            int kk = idx >> 6;
            int n = idx & 63;
            int gk = k0 + kk, gn = bn + n;
            Bs[kk][n] = (gk < K && gn < N) ? W[(size_t)gk * N + gn] : 0.0f;
        }
        __syncthreads();
#pragma unroll
        for (int kk = 0; kk < BK; kk++) {
            float a[8], b[4];
#pragma unroll
            for (int i = 0; i < 8; i++) a[i] = As[kk][tr * 8 + i];
#pragma unroll
            for (int j = 0; j < 4; j++) b[j] = Bs[kk][tc * 4 + j];
#pragma unroll
            for (int i = 0; i < 8; i++)
#pragma unroll
                for (int j = 0; j < 4; j++) acc[i][j] += a[i] * b[j];
        }
        __syncthreads();
    }

#pragma unroll
    for (int i = 0; i < 8; i++) {
        int gm = bm + tr * 8 + i;
        if (gm >= M) continue;
#pragma unroll
        for (int j = 0; j < 4; j++) {
            int gn = bn + tc * 4 + j;
            if (gn >= N) continue;
            C[(size_t)gm * N + gn] = acc[i][j];
        }
    }
}

// ---------------- launch -----------------------------------------------------
extern "C" void kernel_launch(void* const* d_in, const int* in_sizes, int n_in,
                              void* d_out, int out_size) {
    const float* x  = nullptr;
    const float* W0 = nullptr; const float* W1 = nullptr;
    const float* W2 = nullptr; const float* W3 = nullptr;
    const float* b0 = nullptr; const float* b1 = nullptr;
    const float* b2 = nullptr; const float* b3 = nullptr;
    const void*  ei = nullptr;

    int n220 = 0, nbias = 0;
    for (int i = 0; i < n_in; i++) {
        int s = in_sizes[i];
        const void* p = d_in[i];
        switch (s) {
            case 1100000: x  = (const float*)p; break;
            case 4840:    W0 = (const float*)p; break;
            case 48400:   if (n220 == 0) W1 = (const float*)p;
                          else           W2 = (const float*)p;
                          n220++; break;
            case 2200:    W3 = (const float*)p; break;
            case 220:     if (nbias == 0) b0 = (const float*)p;
                          else if (nbias == 1) b1 = (const float*)p;
                          else b2 = (const float*)p;
                          nbias++; break;
            case 10:      b3 = (const float*)p; break;
            case 1600000: ei = p; break;
            default: break;
        }
    }
    float* out = (float*)d_out;

    float *bufA = nullptr, *act = nullptr;
    __half *a16 = nullptr, *a16s = nullptr, *wt16 = nullptr;
    if (cudaGetSymbolAddress((void**)&bufA, g_bufA) != cudaSuccess) return;
    if (cudaGetSymbolAddress((void**)&act, g_act) != cudaSuccess) return;
    if (cudaGetSymbolAddress((void**)&a16, g_a16) != cudaSuccess) return;
    if (cudaGetSymbolAddress((void**)&a16s, g_a16s) != cudaSuccess) return;
    if (cudaGetSymbolAddress((void**)&wt16, g_wt16) != cudaSuccess) return;
    if (!x || !W0 || !W1 || !W2 || !W3 || !b0 || !b1 || !b2 || !b3 || !ei) return;

    const int TB = 256;
    // graph prep
    k_detect<<<1, 32>>>((const int*)ei);
    k_convert<<<(NE + TB - 1) / TB, TB>>>(ei);
    k_init_deg<<<(NN + TB - 1) / TB, TB>>>();
    k_degrees<<<(NE + TB - 1) / TB, TB>>>();
    k_invsqrt<<<(NN + TB - 1) / TB, TB>>>();
    k_scan<<<1, 1024>>>();
    k_fill<<<(NE + TB - 1) / TB, TB>>>();

    const int AGG_BLOCKS = (NN + 7) / 8;  // 8 warps/block
    dim3 mma_grid((220 + 127) / 128, (NNP + 127) / 128);
    dim3 gemm_grid3(1, (NN + 127) / 128);
    const int WT_BLOCKS = (256 * WTS + TB - 1) / TB;
    const int WT0_BLOCKS = (256 * A16S0 + TB - 1) / TB;

    // Layer 0: agg(x)->fp16 a16s (stride 32); WT0; gemm K_eff=32 -> act
    k_aggregate22_h<<<AGG_BLOCKS, TB>>>(x, a16s);
    k_wt16<<<WT0_BLOCKS, TB>>>(W0, wt16, 22, 220, A16S0);
    k_gemm_mma_h16<<<mma_grid, TB>>>(a16s, wt16, b0, act, NN, 220, 32, A16S0);

    // Layer 1: agg fp32->fp16 a16; WT1; gemm K_eff=224 -> act
    k_aggregate220_f32h<<<AGG_BLOCKS, TB>>>(act, a16);
    k_wt16<<<WT_BLOCKS, TB>>>(W1, wt16, 220, 220, WTS);
    k_gemm_mma_h16<<<mma_grid, TB>>>(a16, wt16, b1, act, NN, 220, 224, A16S);

    // Layer 2
    k_aggregate220_f32h<<<AGG_BLOCKS, TB>>>(act, a16);
    k_wt16<<<WT_BLOCKS, TB>>>(W2, wt16, 220, 220, WTS);
    k_gemm_mma_h16<<<mma_grid, TB>>>(a16, wt16, b2, act, NN, 220, 224, A16S);

    // Layer 3 (reordered): z = (h*inv_out) @ W3 -> bufA[N,10]; agg 10-wide + b3
    k_gemm_f<<<gemm_grid3, TB>>>(act, W3, bufA, NN, 220, 10, ACTS);
    k_aggregate<10, false, true><<<AGG_BLOCKS, TB>>>(bufA, out, b3);
}